// round 3
// baseline (speedup 1.0000x reference)
#include <cuda_runtime.h>
#include <cuda_bf16.h>
#include <cstdint>

// ============================ problem constants ============================
#define NROWS   8192
#define BHALF   4096
#define DIM     256
#define TM      128
#define TN      128
#define MBLKS   (NROWS / TM)       // 64
#define NBLKS   (NROWS / TN)       // 64
#define SPLIT   8                  // column groups per M block
#define TILES_PER (NBLKS / SPLIT)  // 8
#define INV_T   14.2857142857142857f   // 1/0.07

// SMEM tile: 128 rows x 264 bf16 (256 data + 8 pad) = 528 B/row -> conflict-free ldmatrix
#define ROW_B   528
#define TILEB   (128 * ROW_B)      // 67584
#define OFF_A   1024               // labs[2][128] ints live at offset 0
#define OFF_B0  (OFF_A + TILEB)    // 68608
#define OFF_B1  (OFF_B0 + TILEB)   // 136192
#define SMEM_BYTES (OFF_B1 + TILEB) // 203776

// ============================ device scratch ============================
__device__ __nv_bfloat16 g_Z[NROWS * DIM];   // normalized rows, bf16
__device__ int   g_lab[NROWS];
__device__ float g_pos[NROWS];
__device__ float g_se[NROWS];

// ============================ PTX helpers (baseline features only) ============================
__device__ __forceinline__ uint32_t smem_to_u32(const void* p) {
    uint32_t a;
    asm("{ .reg .u64 t; cvta.to.shared.u64 t, %1; cvt.u32.u64 %0, t; }" : "=r"(a) : "l"(p));
    return a;
}

#define LDSM_X4(r0, r1, r2, r3, addr) \
    asm volatile("ldmatrix.sync.aligned.m8n8.x4.shared.b16 {%0,%1,%2,%3}, [%4];" \
        : "=r"(r0), "=r"(r1), "=r"(r2), "=r"(r3) : "r"(addr))

#define MMA16816(c, a, b0, b1) \
    asm volatile("mma.sync.aligned.m16n8k16.row.col.f32.bf16.bf16.f32 " \
        "{%0,%1,%2,%3}, {%4,%5,%6,%7}, {%8,%9}, {%0,%1,%2,%3};" \
        : "+f"((c)[0]), "+f"((c)[1]), "+f"((c)[2]), "+f"((c)[3]) \
        : "r"((a)[0]), "r"((a)[1]), "r"((a)[2]), "r"((a)[3]), "r"(b0), "r"(b1))

#define CP_ASYNC16(dst_u32, src_ptr) \
    asm volatile("cp.async.cg.shared.global [%0], [%1], 16;" :: "r"(dst_u32), "l"(src_ptr))
#define CP_COMMIT() asm volatile("cp.async.commit_group;" ::: "memory")
#define CP_WAIT0()  asm volatile("cp.async.wait_group 0;" ::: "memory")

// ============================ kernel 0: decode labels (int32 OR int64) + init ============================
// Reference declares labels int64, but JAX default config (x64 disabled) emits int32.
// Detect from data: int64-LE labels (<1000) have all-zero odd int32 words.
__global__ void k_labels(const int* __restrict__ lab32) {
    __shared__ int stride;
    if (threadIdx.x == 0) {
        int ored = 0;
#pragma unroll
        for (int i = 0; i < 32; i++) ored |= lab32[2 * i + 1];
        stride = (ored == 0) ? 2 : 1;   // all odd words zero -> int64 storage
    }
    __syncthreads();
    int i = blockIdx.x * blockDim.x + threadIdx.x;   // 0..4095
    int v = lab32[i * stride];
    g_lab[i]         = v;
    g_lab[i + BHALF] = v;
    g_pos[i] = 0.f;  g_se[i] = 0.f;
    g_pos[i + BHALF] = 0.f;  g_se[i + BHALF] = 0.f;
}

// ============================ kernel 1: normalize + bf16 ============================
__global__ void k_norm(const float* __restrict__ zi, const float* __restrict__ zj) {
    int row  = blockIdx.x * 8 + (threadIdx.x >> 5);
    int lane = threadIdx.x & 31;
    const float* src = (row < BHALF) ? (zi + (size_t)row * DIM)
                                     : (zj + (size_t)(row - BHALF) * DIM);
    float v[8];
    float ss = 0.f;
#pragma unroll
    for (int i = 0; i < 8; i++) { v[i] = src[i * 32 + lane]; ss += v[i] * v[i]; }
#pragma unroll
    for (int o = 16; o > 0; o >>= 1) ss += __shfl_xor_sync(0xffffffffu, ss, o);
    float inv = 1.f / fmaxf(sqrtf(ss), 1e-12f);
    __nv_bfloat16* dst = g_Z + (size_t)row * DIM;
#pragma unroll
    for (int i = 0; i < 8; i++) dst[i * 32 + lane] = __float2bfloat16(v[i] * inv);
}

// ============================ kernel 2: GEMM (mma.sync) + fused masked epilogue ============================
// cp.async a 128x256 bf16 tile (gmem row-major, 512B/row) into padded SMEM (528B/row)
__device__ __forceinline__ void cpasync_tile(uint32_t dst, const __nv_bfloat16* src, int tid) {
#pragma unroll
    for (int it = 0; it < 16; it++) {
        int idx = tid + it * 256;        // 0..4095 16B-chunks
        int row = idx >> 5, c = idx & 31;
        const char* s = reinterpret_cast<const char*>(src) + row * 512 + c * 16;
        CP_ASYNC16(dst + row * ROW_B + c * 16, s);
    }
}

__global__ void __launch_bounds__(256, 1) k_sim() {
    extern __shared__ char smem[];
    uint32_t su  = smem_to_u32(smem);
    int* labs = reinterpret_cast<int*>(smem);     // [2][128]

    int tid  = threadIdx.x;
    int lane = tid & 31;
    int wid  = tid >> 5;
    int mb   = blockIdx.y;        // row block (0..63)
    int cg   = blockIdx.x;        // column group (0..7)
    const int wm = (wid >> 2) * 64;   // warp m-offset within tile
    const int wn = (wid & 3) * 32;    // warp n-offset within tile
    const int g  = lane >> 2;         // group id 0..7
    const int t  = lane & 3;          // thread in group

    // prologue: A tile + first B tile + labels
    cpasync_tile(su + OFF_A,  g_Z + (size_t)mb * TM * DIM, tid);
    int nb0 = cg * TILES_PER;
    cpasync_tile(su + OFF_B0, g_Z + (size_t)nb0 * TN * DIM, tid);
    CP_COMMIT();
    if (tid < 128) labs[tid] = g_lab[nb0 * TN + tid];

    // row labels / global row ids for this lane's 8 row-slots
    int lab_row[8], row_g[8];
#pragma unroll
    for (int s = 0; s < 8; s++) {
        int mt = s >> 1, h = s & 1;
        row_g[s]   = mb * TM + wm + mt * 16 + g + 8 * h;
        lab_row[s] = g_lab[row_g[s]];
    }
    float pos[8], se[8];
#pragma unroll
    for (int s = 0; s < 8; s++) { pos[s] = 0.f; se[s] = 0.f; }

    CP_WAIT0();
    __syncthreads();

    for (int tt = 0; tt < TILES_PER; tt++) {
        int nb = cg * TILES_PER + tt;
        uint32_t bbuf = su + ((tt & 1) ? OFF_B1 : OFF_B0);

        // prefetch next B tile + its labels into the other buffer
        if (tt + 1 < TILES_PER) {
            cpasync_tile(su + (((tt + 1) & 1) ? OFF_B1 : OFF_B0),
                         g_Z + (size_t)(nb + 1) * TN * DIM, tid);
            CP_COMMIT();
            if (tid < 128) labs[((tt + 1) & 1) * 128 + tid] = g_lab[(nb + 1) * TN + tid];
        }

        // ---- GEMM: warp computes 64x32, K=256 ----
        float c[4][4][4];
#pragma unroll
        for (int mt = 0; mt < 4; mt++)
#pragma unroll
            for (int nt = 0; nt < 4; nt++)
#pragma unroll
                for (int i = 0; i < 4; i++) c[mt][nt][i] = 0.f;

#pragma unroll
        for (int kk = 0; kk < 16; kk++) {
            int kb = (kk * 16 + ((lane >> 4) << 3)) * 2;   // byte offset in row
            uint32_t a[4][4], b[2][4];
#pragma unroll
            for (int mt = 0; mt < 4; mt++) {
                uint32_t addr = su + OFF_A + (wm + mt * 16 + (lane & 15)) * ROW_B + kb;
                LDSM_X4(a[mt][0], a[mt][1], a[mt][2], a[mt][3], addr);
            }
#pragma unroll
            for (int p = 0; p < 2; p++) {
                uint32_t addr = bbuf + (wn + p * 16 + (lane & 15)) * ROW_B + kb;
                LDSM_X4(b[p][0], b[p][1], b[p][2], b[p][3], addr);
            }
#pragma unroll
            for (int mt = 0; mt < 4; mt++)
#pragma unroll
                for (int nt = 0; nt < 4; nt++)
                    MMA16816(c[mt][nt], a[mt], b[nt >> 1][nt & 1], b[nt >> 1][2 + (nt & 1)]);
        }

        // ---- fused epilogue on register fragments ----
        const int* lb = labs + (tt & 1) * 128;
#pragma unroll
        for (int mt = 0; mt < 4; mt++)
#pragma unroll
            for (int nt = 0; nt < 4; nt++)
#pragma unroll
                for (int i = 0; i < 4; i++) {
                    int s    = mt * 2 + (i >> 1);
                    int coll = wn + nt * 8 + t * 2 + (i & 1);      // col within tile
                    float v  = c[mt][nt][i] * INV_T;
                    if (lb[coll] == lab_row[s]) {
                        if (nb * TN + coll != row_g[s]) pos[s] += v;   // positive, not self
                    } else {
                        se[s] += __expf(v);                             // negative
                    }
                }

        if (tt + 1 < TILES_PER) CP_WAIT0();
        __syncthreads();
    }

    // reduce over the 4-lane group (same rows, different cols), one atomic per row
#pragma unroll
    for (int s = 0; s < 8; s++) {
        float p = pos[s], e = se[s];
        p += __shfl_xor_sync(0xffffffffu, p, 1);
        p += __shfl_xor_sync(0xffffffffu, p, 2);
        e += __shfl_xor_sync(0xffffffffu, e, 1);
        e += __shfl_xor_sync(0xffffffffu, e, 2);
        if (t == 0) {
            atomicAdd(&g_pos[row_g[s]], p);
            atomicAdd(&g_se[row_g[s]],  e);
        }
    }
}

// ============================ kernel 3: final reduction ============================
__global__ void k_final(float* __restrict__ out) {
    __shared__ float red[32];
    float acc = 0.f;
    for (int r = threadIdx.x; r < NROWS; r += 1024) {
        // loss_i = logaddexp(0, lse_neg - pos_sim); |sim|<=14.3 so sum-exp is fp32-safe
        float x  = logf(g_se[r]) - g_pos[r];
        float li = (x > 0.f) ? (x + log1pf(expf(-x))) : log1pf(expf(x));
        acc += li;   // every row has a positive (its augmented pair), so has_pos is always true
    }
#pragma unroll
    for (int o = 16; o > 0; o >>= 1) acc += __shfl_xor_sync(0xffffffffu, acc, o);
    if ((threadIdx.x & 31) == 0) red[threadIdx.x >> 5] = acc;
    __syncthreads();
    if (threadIdx.x < 32) {
        float a = red[threadIdx.x];
#pragma unroll
        for (int o = 16; o > 0; o >>= 1) a += __shfl_xor_sync(0xffffffffu, a, o);
        if (threadIdx.x == 0) out[0] = a * (1.0f / (float)NROWS);
    }
}

// ============================ launch ============================
extern "C" void kernel_launch(void* const* d_in, const int* in_sizes, int n_in,
                              void* d_out, int out_size) {
    (void)in_sizes; (void)n_in; (void)out_size;
    const float* zi  = (const float*)d_in[0];
    const float* zj  = (const float*)d_in[1];
    const int*   lab = (const int*)d_in[2];    // int32 or int64; k_labels auto-detects

    cudaFuncSetAttribute(k_sim, cudaFuncAttributeMaxDynamicSharedMemorySize, SMEM_BYTES);

    k_labels<<<BHALF / 256, 256>>>(lab);
    k_norm<<<NROWS / 8, 256>>>(zi, zj);
    dim3 grid(SPLIT, MBLKS);
    k_sim<<<grid, 256, SMEM_BYTES>>>();
    k_final<<<1, 1024>>>((float*)d_out);
}

// round 4
// speedup vs baseline: 1.5501x; 1.5501x over previous
#include <cuda_runtime.h>
#include <cuda_bf16.h>
#include <cstdint>

// ============================ problem constants ============================
#define NROWS   8192
#define BHALF   4096
#define DIM     256
#define TM      128
#define TN      128
#define MBLKS   (NROWS / TM)       // 64
#define INV_T   14.2857142857142857f   // 1/0.07

// SMEM tile: 128 rows x 264 bf16 (256 data + 8 pad) = 528 B/row -> conflict-free ldmatrix
#define ROW_B   528
#define TILEB   (128 * ROW_B)      // 67584
#define OFF_A   1024               // labs[2][128] ints live at offset 0
#define OFF_B0  (OFF_A + TILEB)    // 68608
#define OFF_B1  (OFF_B0 + TILEB)   // 136192
#define SMEM_BYTES (OFF_B1 + TILEB) // 203776

// ============================ device scratch ============================
__device__ __nv_bfloat16 g_Z[NROWS * DIM];   // normalized rows, bf16
__device__ int   g_lab[NROWS];
__device__ float g_pos[NROWS];
__device__ float g_se[NROWS];

// ============================ PTX helpers (baseline features only) ============================
__device__ __forceinline__ uint32_t smem_to_u32(const void* p) {
    uint32_t a;
    asm("{ .reg .u64 t; cvta.to.shared.u64 t, %1; cvt.u32.u64 %0, t; }" : "=r"(a) : "l"(p));
    return a;
}

#define LDSM_X4(r0, r1, r2, r3, addr) \
    asm volatile("ldmatrix.sync.aligned.m8n8.x4.shared.b16 {%0,%1,%2,%3}, [%4];" \
        : "=r"(r0), "=r"(r1), "=r"(r2), "=r"(r3) : "r"(addr))

#define MMA16816(c, a, b0, b1) \
    asm volatile("mma.sync.aligned.m16n8k16.row.col.f32.bf16.bf16.f32 " \
        "{%0,%1,%2,%3}, {%4,%5,%6,%7}, {%8,%9}, {%0,%1,%2,%3};" \
        : "+f"((c)[0]), "+f"((c)[1]), "+f"((c)[2]), "+f"((c)[3]) \
        : "r"((a)[0]), "r"((a)[1]), "r"((a)[2]), "r"((a)[3]), "r"(b0), "r"(b1))

#define CP_ASYNC16(dst_u32, src_ptr) \
    asm volatile("cp.async.cg.shared.global [%0], [%1], 16;" :: "r"(dst_u32), "l"(src_ptr))
#define CP_COMMIT() asm volatile("cp.async.commit_group;" ::: "memory")
#define CP_WAIT0()  asm volatile("cp.async.wait_group 0;" ::: "memory")

// ============================ kernel 0: decode labels (int32 OR int64) + init ============================
// Reference declares labels int64, but JAX default config (x64 disabled) emits int32.
// Detect from data: int64-LE labels (<1000) have all-zero odd int32 words.
__global__ void k_labels(const int* __restrict__ lab32, float* __restrict__ out) {
    __shared__ int stride;
    if (threadIdx.x == 0) {
        int ored = 0;
#pragma unroll
        for (int i = 0; i < 32; i++) ored |= lab32[2 * i + 1];
        stride = (ored == 0) ? 2 : 1;   // all odd words zero -> int64 storage
        if (blockIdx.x == 0) out[0] = 0.f;
    }
    __syncthreads();
    int i = blockIdx.x * blockDim.x + threadIdx.x;   // 0..4095
    int v = lab32[i * stride];
    g_lab[i]         = v;
    g_lab[i + BHALF] = v;
    g_pos[i] = 0.f;  g_se[i] = 0.f;
    g_pos[i + BHALF] = 0.f;  g_se[i + BHALF] = 0.f;
}

// ============================ kernel 1: normalize + bf16 ============================
__global__ void k_norm(const float* __restrict__ zi, const float* __restrict__ zj) {
    int row  = blockIdx.x * 8 + (threadIdx.x >> 5);
    int lane = threadIdx.x & 31;
    const float* src = (row < BHALF) ? (zi + (size_t)row * DIM)
                                     : (zj + (size_t)(row - BHALF) * DIM);
    float v[8];
    float ss = 0.f;
#pragma unroll
    for (int i = 0; i < 8; i++) { v[i] = src[i * 32 + lane]; ss += v[i] * v[i]; }
#pragma unroll
    for (int o = 16; o > 0; o >>= 1) ss += __shfl_xor_sync(0xffffffffu, ss, o);
    float inv = 1.f / fmaxf(sqrtf(ss), 1e-12f);
    __nv_bfloat16* dst = g_Z + (size_t)row * DIM;
#pragma unroll
    for (int i = 0; i < 8; i++) dst[i * 32 + lane] = __float2bfloat16(v[i] * inv);
}

// ============================ kernel 2: symmetric GEMM + fused dual epilogue ============================
// Circulant triangle: tile (i, (i+d) & 63), d = 0..31 for all i, d = 32 for i < 32
// -> each unordered block pair exactly once (2080 tiles vs 4096 full).
__device__ __forceinline__ void cpasync_tile(uint32_t dst, const __nv_bfloat16* src, int tid) {
#pragma unroll
    for (int it = 0; it < 16; it++) {
        int idx = tid + it * 256;        // 0..4095 16B-chunks
        int row = idx >> 5, c = idx & 31;
        const char* s = reinterpret_cast<const char*>(src) + row * 512 + c * 16;
        CP_ASYNC16(dst + row * ROW_B + c * 16, s);
    }
}

__global__ void __launch_bounds__(256, 1) k_sim() {
    extern __shared__ char smem[];
    uint32_t su = smem_to_u32(smem);
    int* labs = reinterpret_cast<int*>(smem);     // [2][128]

    int tid  = threadIdx.x;
    int lane = tid & 31;
    int wid  = tid >> 5;
    int ib   = blockIdx.y;        // row block (0..63)
    int cg   = blockIdx.x;        // d-chunk (0..7)
    const int wm = (wid >> 2) * 64;   // warp m-offset within tile
    const int wn = (wid & 3) * 32;    // warp n-offset within tile
    const int g  = lane >> 2;
    const int t  = lane & 3;

    // d-list for this CTA
    int dlist[5];
    int ntile = 4;
    dlist[0] = cg * 4; dlist[1] = cg * 4 + 1; dlist[2] = cg * 4 + 2; dlist[3] = cg * 4 + 3;
    if (cg == 0 && ib < 32) dlist[ntile++] = 32;

    // prologue: A tile; first B tile (skip if diag: d==0 reuses A); labels for j0
    cpasync_tile(su + OFF_A, g_Z + (size_t)ib * TM * DIM, tid);
    int j0 = (ib + dlist[0]) & 63;
    if (dlist[0] != 0) cpasync_tile(su + OFF_B0, g_Z + (size_t)j0 * TN * DIM, tid);
    CP_COMMIT();
    if (tid < 128) labs[tid] = g_lab[j0 * TN + tid];

    // row labels / global row ids for this lane's 8 row-slots
    int lab_row[8], row_g[8];
#pragma unroll
    for (int s = 0; s < 8; s++) {
        int mt = s >> 1, h = s & 1;
        row_g[s]   = ib * TM + wm + mt * 16 + g + 8 * h;
        lab_row[s] = g_lab[row_g[s]];
    }
    float pos[8], se[8];
#pragma unroll
    for (int s = 0; s < 8; s++) { pos[s] = 0.f; se[s] = 0.f; }

    CP_WAIT0();
    __syncthreads();

    for (int k = 0; k < ntile; k++) {
        int d = dlist[k];
        int jb = (ib + d) & 63;
        uint32_t bbuf = (d == 0) ? (su + OFF_A) : (su + ((k & 1) ? OFF_B1 : OFF_B0));

        // prefetch next tile's B + labels (next d is always > 0)
        if (k + 1 < ntile) {
            int jn = (ib + dlist[k + 1]) & 63;
            cpasync_tile(su + (((k + 1) & 1) ? OFF_B1 : OFF_B0),
                         g_Z + (size_t)jn * TN * DIM, tid);
            CP_COMMIT();
            if (tid < 128) labs[((k + 1) & 1) * 128 + tid] = g_lab[jn * TN + tid];
        }

        // ---- GEMM: warp computes 64x32, K=256 ----
        float c[4][4][4];
#pragma unroll
        for (int mt = 0; mt < 4; mt++)
#pragma unroll
            for (int nt = 0; nt < 4; nt++)
#pragma unroll
                for (int i = 0; i < 4; i++) c[mt][nt][i] = 0.f;

#pragma unroll
        for (int kk = 0; kk < 16; kk++) {
            int kb = (kk * 16 + ((lane >> 4) << 3)) * 2;   // byte offset in row
            uint32_t a[4][4], b[2][4];
#pragma unroll
            for (int mt = 0; mt < 4; mt++) {
                uint32_t addr = su + OFF_A + (wm + mt * 16 + (lane & 15)) * ROW_B + kb;
                LDSM_X4(a[mt][0], a[mt][1], a[mt][2], a[mt][3], addr);
            }
#pragma unroll
            for (int p = 0; p < 2; p++) {
                uint32_t addr = bbuf + (wn + p * 16 + (lane & 15)) * ROW_B + kb;
                LDSM_X4(b[p][0], b[p][1], b[p][2], b[p][3], addr);
            }
#pragma unroll
            for (int mt = 0; mt < 4; mt++)
#pragma unroll
                for (int nt = 0; nt < 4; nt++)
                    MMA16816(c[mt][nt], a[mt], b[nt >> 1][nt & 1], b[nt >> 1][2 + (nt & 1)]);
        }

        // ---- fused epilogue ----
        const int* lb = labs + (k & 1) * 128;
        if (d == 0) {
            // diagonal tile: row accumulation only, with self exclusion
#pragma unroll
            for (int mt = 0; mt < 4; mt++)
#pragma unroll
                for (int nt = 0; nt < 4; nt++)
#pragma unroll
                    for (int i = 0; i < 4; i++) {
                        int s    = mt * 2 + (i >> 1);
                        int coll = wn + nt * 8 + t * 2 + (i & 1);
                        float v  = c[mt][nt][i] * INV_T;
                        if (lb[coll] == lab_row[s]) {
                            if (jb * TN + coll != row_g[s]) pos[s] += v;
                        } else {
                            se[s] += __expf(v);
                        }
                    }
        } else {
            // off-diagonal: dual accumulation (rows of block ib, and mirrored rows of block jb)
            float cpos[8], cse[8];
#pragma unroll
            for (int ci = 0; ci < 8; ci++) { cpos[ci] = 0.f; cse[ci] = 0.f; }
#pragma unroll
            for (int mt = 0; mt < 4; mt++)
#pragma unroll
                for (int nt = 0; nt < 4; nt++)
#pragma unroll
                    for (int i = 0; i < 4; i++) {
                        int s    = mt * 2 + (i >> 1);
                        int ci   = nt * 2 + (i & 1);
                        int coll = wn + nt * 8 + t * 2 + (i & 1);
                        float v  = c[mt][nt][i] * INV_T;
                        if (lb[coll] == lab_row[s]) {
                            pos[s] += v;  cpos[ci] += v;
                        } else {
                            float e = __expf(v);
                            se[s] += e;   cse[ci] += e;
                        }
                    }
            // reduce col partials across the 8 row-groups (g), then flush with atomics
#pragma unroll
            for (int ci = 0; ci < 8; ci++) {
                float p = cpos[ci], e = cse[ci];
                p += __shfl_xor_sync(0xffffffffu, p, 4);
                p += __shfl_xor_sync(0xffffffffu, p, 8);
                p += __shfl_xor_sync(0xffffffffu, p, 16);
                e += __shfl_xor_sync(0xffffffffu, e, 4);
                e += __shfl_xor_sync(0xffffffffu, e, 8);
                e += __shfl_xor_sync(0xffffffffu, e, 16);
                if (lane < 4) {
                    int col = wn + (ci >> 1) * 8 + lane * 2 + (ci & 1);
                    atomicAdd(&g_pos[jb * TN + col], p);
                    atomicAdd(&g_se[jb * TN + col],  e);
                }
            }
        }

        if (k + 1 < ntile) CP_WAIT0();
        __syncthreads();
    }

    // flush row accumulators: reduce over the 4-lane group, one atomic per row
#pragma unroll
    for (int s = 0; s < 8; s++) {
        float p = pos[s], e = se[s];
        p += __shfl_xor_sync(0xffffffffu, p, 1);
        p += __shfl_xor_sync(0xffffffffu, p, 2);
        e += __shfl_xor_sync(0xffffffffu, e, 1);
        e += __shfl_xor_sync(0xffffffffu, e, 2);
        if (t == 0) {
            atomicAdd(&g_pos[row_g[s]], p);
            atomicAdd(&g_se[row_g[s]],  e);
        }
    }
}

// ============================ kernel 3: final reduction (8 CTAs + atomic merge) ============================
__global__ void k_final(float* __restrict__ out) {
    __shared__ float red[32];
    int r = blockIdx.x * 1024 + threadIdx.x;
    // loss_i = logaddexp(0, lse_neg - pos_sim); |sim|<=14.3 so sum-exp is fp32-safe
    float x  = logf(g_se[r]) - g_pos[r];
    float li = (x > 0.f) ? (x + log1pf(expf(-x))) : log1pf(expf(x));
#pragma unroll
    for (int o = 16; o > 0; o >>= 1) li += __shfl_xor_sync(0xffffffffu, li, o);
    if ((threadIdx.x & 31) == 0) red[threadIdx.x >> 5] = li;
    __syncthreads();
    if (threadIdx.x < 32) {
        float a = red[threadIdx.x];
#pragma unroll
        for (int o = 16; o > 0; o >>= 1) a += __shfl_xor_sync(0xffffffffu, a, o);
        if (threadIdx.x == 0) atomicAdd(out, a * (1.0f / (float)NROWS));
    }
}

// ============================ launch ============================
extern "C" void kernel_launch(void* const* d_in, const int* in_sizes, int n_in,
                              void* d_out, int out_size) {
    (void)in_sizes; (void)n_in; (void)out_size;
    const float* zi  = (const float*)d_in[0];
    const float* zj  = (const float*)d_in[1];
    const int*   lab = (const int*)d_in[2];    // int32 or int64; k_labels auto-detects

    cudaFuncSetAttribute(k_sim, cudaFuncAttributeMaxDynamicSharedMemorySize, SMEM_BYTES);

    k_labels<<<BHALF / 256, 256>>>(lab, (float*)d_out);
    k_norm<<<NROWS / 8, 256>>>(zi, zj);
    dim3 grid(8, MBLKS);
    k_sim<<<grid, 256, SMEM_BYTES>>>();
    k_final<<<NROWS / 1024, 1024>>>((float*)d_out);
}

// round 5
// speedup vs baseline: 2.0771x; 1.3399x over previous
#include <cuda_runtime.h>
#include <cuda_bf16.h>
#include <cstdint>

// ============================ problem constants ============================
#define NROWS   8192
#define BHALF   4096
#define DIM     256
#define TM      128
#define TN      128
#define INV_T   14.2857142857142857f   // 1/0.07

#define NCTA    148
#define NTILES  2080        // circulant upper triangle of 64x64 blocks

// SMEM tile: 128 rows x 264 bf16 (256 data + 8 pad) = 528 B/row -> conflict-free ldmatrix
#define ROW_B   528
#define TILEB   (128 * ROW_B)      // 67584
#define OFF_A   1024               // labs[2][128] ints live at offset 0
#define OFF_B0  (OFF_A + TILEB)    // 68608
#define OFF_B1  (OFF_B0 + TILEB)   // 136192
#define SMEM_BYTES (OFF_B1 + TILEB) // 203776

// ============================ device scratch ============================
__device__ __nv_bfloat16 g_Z[NROWS * DIM];   // normalized rows, bf16
__device__ int   g_lab[NROWS];
__device__ float g_pos[NROWS];
__device__ float g_se[NROWS];

// ============================ PTX helpers (baseline features only) ============================
__device__ __forceinline__ uint32_t smem_to_u32(const void* p) {
    uint32_t a;
    asm("{ .reg .u64 t; cvta.to.shared.u64 t, %1; cvt.u32.u64 %0, t; }" : "=r"(a) : "l"(p));
    return a;
}

#define LDSM_X4(r0, r1, r2, r3, addr) \
    asm volatile("ldmatrix.sync.aligned.m8n8.x4.shared.b16 {%0,%1,%2,%3}, [%4];" \
        : "=r"(r0), "=r"(r1), "=r"(r2), "=r"(r3) : "r"(addr))

#define MMA16816(c, a, b0, b1) \
    asm volatile("mma.sync.aligned.m16n8k16.row.col.f32.bf16.bf16.f32 " \
        "{%0,%1,%2,%3}, {%4,%5,%6,%7}, {%8,%9}, {%0,%1,%2,%3};" \
        : "+f"((c)[0]), "+f"((c)[1]), "+f"((c)[2]), "+f"((c)[3]) \
        : "r"((a)[0]), "r"((a)[1]), "r"((a)[2]), "r"((a)[3]), "r"(b0), "r"(b1))

#define CP_ASYNC16(dst_u32, src_ptr) \
    asm volatile("cp.async.cg.shared.global [%0], [%1], 16;" :: "r"(dst_u32), "l"(src_ptr))
#define CP_COMMIT() asm volatile("cp.async.commit_group;" ::: "memory")
#define CP_WAIT0()  asm volatile("cp.async.wait_group 0;" ::: "memory")

// tile t -> (ib, d); jb = (ib + d) & 63. ib<32 has d=0..32 (33 tiles), ib>=32 has d=0..31.
__device__ __forceinline__ void decode_tile(int t, int& ib, int& d) {
    if (t < 32 * 33) { ib = t / 33; d = t - ib * 33; }
    else { int u = t - 32 * 33; ib = 32 + (u >> 5); d = u & 31; }
}

// ============================ kernel 0: decode labels (int32 OR int64) + init ============================
// Reference declares labels int64, but JAX default config (x64 disabled) emits int32.
// Detect from data: int64-LE labels (<1000) have all-zero odd int32 words.
__global__ void k_labels(const int* __restrict__ lab32, float* __restrict__ out) {
    __shared__ int stride;
    if (threadIdx.x == 0) {
        int ored = 0;
#pragma unroll
        for (int i = 0; i < 32; i++) ored |= lab32[2 * i + 1];
        stride = (ored == 0) ? 2 : 1;   // all odd words zero -> int64 storage
        if (blockIdx.x == 0) out[0] = 0.f;
    }
    __syncthreads();
    int i = blockIdx.x * blockDim.x + threadIdx.x;   // 0..4095
    int v = lab32[i * stride];
    g_lab[i]         = v;
    g_lab[i + BHALF] = v;
    g_pos[i] = 0.f;  g_se[i] = 0.f;
    g_pos[i + BHALF] = 0.f;  g_se[i + BHALF] = 0.f;
}

// ============================ kernel 1: normalize + bf16 ============================
__global__ void k_norm(const float* __restrict__ zi, const float* __restrict__ zj) {
    int row  = blockIdx.x * 8 + (threadIdx.x >> 5);
    int lane = threadIdx.x & 31;
    const float* src = (row < BHALF) ? (zi + (size_t)row * DIM)
                                     : (zj + (size_t)(row - BHALF) * DIM);
    float v[8];
    float ss = 0.f;
#pragma unroll
    for (int i = 0; i < 8; i++) { v[i] = src[i * 32 + lane]; ss += v[i] * v[i]; }
#pragma unroll
    for (int o = 16; o > 0; o >>= 1) ss += __shfl_xor_sync(0xffffffffu, ss, o);
    float inv = 1.f / fmaxf(sqrtf(ss), 1e-12f);
    __nv_bfloat16* dst = g_Z + (size_t)row * DIM;
#pragma unroll
    for (int i = 0; i < 8; i++) dst[i * 32 + lane] = __float2bfloat16(v[i] * inv);
}

// ============================ kernel 2: symmetric GEMM, persistent balanced CTAs ============================
__device__ __forceinline__ void cpasync_tile(uint32_t dst, const __nv_bfloat16* src, int tid) {
#pragma unroll
    for (int it = 0; it < 8; it++) {
        int idx = tid + it * 512;        // 0..4095 16B-chunks
        int row = idx >> 5, c = idx & 31;
        const char* s = reinterpret_cast<const char*>(src) + row * 512 + c * 16;
        CP_ASYNC16(dst + row * ROW_B + c * 16, s);
    }
}

__global__ void __launch_bounds__(512, 1) k_sim() {
    extern __shared__ char smem[];
    uint32_t su = smem_to_u32(smem);
    int* labs = reinterpret_cast<int*>(smem);     // [2][128]

    int tid  = threadIdx.x;
    int lane = tid & 31;
    int wid  = tid >> 5;                 // 0..15
    const int wm = (wid >> 2) * 32;      // warp m-offset (4 bands of 32 rows)
    const int wn = (wid & 3) * 32;       // warp n-offset (4 bands of 32 cols)
    const int g  = lane >> 2;
    const int t4 = lane & 3;

    int cta = blockIdx.x;
    int t0 = (cta * NTILES) / NCTA;
    int t1 = ((cta + 1) * NTILES) / NCTA;

    // pre-loop: prefetch first tile's B + labels into buffer 0
    {
        int ib0, d0; decode_tile(t0, ib0, d0);
        int jb0 = (ib0 + d0) & 63;
        if (d0 != 0) cpasync_tile(su + OFF_B0, g_Z + (size_t)jb0 * TN * DIM, tid);
        CP_COMMIT();
        if (tid < 128) labs[tid] = g_lab[jb0 * TN + tid];
    }

    int cur_ib = -1;
    int lab_row[4], row_g[4];
    float pos[4], se[4];

    for (int t = t0; t < t1; t++) {
        int ib, d; decode_tile(t, ib, d);
        int jb  = (ib + d) & 63;
        int buf = (t - t0) & 1;

        if (ib != cur_ib) {
            // flush row accumulators of the previous ib
            if (cur_ib >= 0) {
#pragma unroll
                for (int s = 0; s < 4; s++) {
                    float p = pos[s], e = se[s];
                    p += __shfl_xor_sync(0xffffffffu, p, 1);
                    p += __shfl_xor_sync(0xffffffffu, p, 2);
                    e += __shfl_xor_sync(0xffffffffu, e, 1);
                    e += __shfl_xor_sync(0xffffffffu, e, 2);
                    if (t4 == 0) {
                        atomicAdd(&g_pos[row_g[s]], p);
                        atomicAdd(&g_se[row_g[s]],  e);
                    }
                }
            }
            cpasync_tile(su + OFF_A, g_Z + (size_t)ib * TM * DIM, tid);
            CP_COMMIT();
            CP_WAIT0();            // also drains any in-flight B prefetch
            __syncthreads();
            cur_ib = ib;
#pragma unroll
            for (int s = 0; s < 4; s++) {
                int mt = s >> 1, h = s & 1;
                row_g[s]   = ib * TM + wm + mt * 16 + g + 8 * h;
                lab_row[s] = g_lab[row_g[s]];
                pos[s] = 0.f;  se[s] = 0.f;
            }
        }

        uint32_t bbuf = (d == 0) ? (su + OFF_A) : (su + (buf ? OFF_B1 : OFF_B0));

        // prefetch next tile's B + labels
        if (t + 1 < t1) {
            int ibn, dn; decode_tile(t + 1, ibn, dn);
            int jn = (ibn + dn) & 63;
            if (dn != 0) cpasync_tile(su + ((buf ^ 1) ? OFF_B1 : OFF_B0),
                                      g_Z + (size_t)jn * TN * DIM, tid);
            CP_COMMIT();
            if (tid < 128) labs[(buf ^ 1) * 128 + tid] = g_lab[jn * TN + tid];
        }

        // ---- GEMM: warp computes 32x32, K=256 ----
        float c[2][4][4];
#pragma unroll
        for (int mt = 0; mt < 2; mt++)
#pragma unroll
            for (int nt = 0; nt < 4; nt++)
#pragma unroll
                for (int i = 0; i < 4; i++) c[mt][nt][i] = 0.f;

#pragma unroll
        for (int kk = 0; kk < 16; kk++) {
            int kb = (kk * 16 + ((lane >> 4) << 3)) * 2;   // byte offset in row
            uint32_t a[2][4], b[2][4];
#pragma unroll
            for (int mt = 0; mt < 2; mt++) {
                uint32_t addr = su + OFF_A + (wm + mt * 16 + (lane & 15)) * ROW_B + kb;
                LDSM_X4(a[mt][0], a[mt][1], a[mt][2], a[mt][3], addr);
            }
#pragma unroll
            for (int p = 0; p < 2; p++) {
                uint32_t addr = bbuf + (wn + p * 16 + (lane & 15)) * ROW_B + kb;
                LDSM_X4(b[p][0], b[p][1], b[p][2], b[p][3], addr);
            }
#pragma unroll
            for (int mt = 0; mt < 2; mt++)
#pragma unroll
                for (int nt = 0; nt < 4; nt++)
                    MMA16816(c[mt][nt], a[mt], b[nt >> 1][nt & 1], b[nt >> 1][2 + (nt & 1)]);
        }

        // ---- fused epilogue ----
        const int* lb = labs + buf * 128;
        if (d == 0) {
            // diagonal tile: row accumulation only, with self exclusion
#pragma unroll
            for (int mt = 0; mt < 2; mt++)
#pragma unroll
                for (int nt = 0; nt < 4; nt++)
#pragma unroll
                    for (int i = 0; i < 4; i++) {
                        int s    = mt * 2 + (i >> 1);
                        int coll = wn + nt * 8 + t4 * 2 + (i & 1);
                        float v  = c[mt][nt][i] * INV_T;
                        if (lb[coll] == lab_row[s]) {
                            if (jb * TN + coll != row_g[s]) pos[s] += v;
                        } else {
                            se[s] += __expf(v);
                        }
                    }
        } else {
            // off-diagonal: dual accumulation (rows of block ib, mirrored rows of block jb)
            float cpos[8], cse[8];
#pragma unroll
            for (int ci = 0; ci < 8; ci++) { cpos[ci] = 0.f; cse[ci] = 0.f; }
#pragma unroll
            for (int mt = 0; mt < 2; mt++)
#pragma unroll
                for (int nt = 0; nt < 4; nt++)
#pragma unroll
                    for (int i = 0; i < 4; i++) {
                        int s    = mt * 2 + (i >> 1);
                        int ci   = nt * 2 + (i & 1);
                        int coll = wn + nt * 8 + t4 * 2 + (i & 1);
                        float v  = c[mt][nt][i] * INV_T;
                        if (lb[coll] == lab_row[s]) {
                            pos[s] += v;  cpos[ci] += v;
                        } else {
                            float e = __expf(v);
                            se[s] += e;   cse[ci] += e;
                        }
                    }
            // reduce col partials across the 8 row-groups (g), flush with atomics
#pragma unroll
            for (int ci = 0; ci < 8; ci++) {
                float p = cpos[ci], e = cse[ci];
                p += __shfl_xor_sync(0xffffffffu, p, 4);
                p += __shfl_xor_sync(0xffffffffu, p, 8);
                p += __shfl_xor_sync(0xffffffffu, p, 16);
                e += __shfl_xor_sync(0xffffffffu, e, 4);
                e += __shfl_xor_sync(0xffffffffu, e, 8);
                e += __shfl_xor_sync(0xffffffffu, e, 16);
                if (lane < 4) {
                    int col = wn + (ci >> 1) * 8 + lane * 2 + (ci & 1);
                    atomicAdd(&g_pos[jb * TN + col], p);
                    atomicAdd(&g_se[jb * TN + col],  e);
                }
            }
        }

        CP_WAIT0();
        __syncthreads();
    }

    // final flush of row accumulators
    if (cur_ib >= 0) {
#pragma unroll
        for (int s = 0; s < 4; s++) {
            float p = pos[s], e = se[s];
            p += __shfl_xor_sync(0xffffffffu, p, 1);
            p += __shfl_xor_sync(0xffffffffu, p, 2);
            e += __shfl_xor_sync(0xffffffffu, e, 1);
            e += __shfl_xor_sync(0xffffffffu, e, 2);
            if (t4 == 0) {
                atomicAdd(&g_pos[row_g[s]], p);
                atomicAdd(&g_se[row_g[s]],  e);
            }
        }
    }
}

// ============================ kernel 3: final reduction (8 CTAs + atomic merge) ============================
__global__ void k_final(float* __restrict__ out) {
    __shared__ float red[32];
    int r = blockIdx.x * 1024 + threadIdx.x;
    // loss_i = logaddexp(0, lse_neg - pos_sim); |sim|<=14.3 so sum-exp is fp32-safe
    float x  = logf(g_se[r]) - g_pos[r];
    float li = (x > 0.f) ? (x + log1pf(expf(-x))) : log1pf(expf(x));
#pragma unroll
    for (int o = 16; o > 0; o >>= 1) li += __shfl_xor_sync(0xffffffffu, li, o);
    if ((threadIdx.x & 31) == 0) red[threadIdx.x >> 5] = li;
    __syncthreads();
    if (threadIdx.x < 32) {
        float a = red[threadIdx.x];
#pragma unroll
        for (int o = 16; o > 0; o >>= 1) a += __shfl_xor_sync(0xffffffffu, a, o);
        if (threadIdx.x == 0) atomicAdd(out, a * (1.0f / (float)NROWS));
    }
}

// ============================ launch ============================
extern "C" void kernel_launch(void* const* d_in, const int* in_sizes, int n_in,
                              void* d_out, int out_size) {
    (void)in_sizes; (void)n_in; (void)out_size;
    const float* zi  = (const float*)d_in[0];
    const float* zj  = (const float*)d_in[1];
    const int*   lab = (const int*)d_in[2];    // int32 or int64; k_labels auto-detects

    cudaFuncSetAttribute(k_sim, cudaFuncAttributeMaxDynamicSharedMemorySize, SMEM_BYTES);

    k_labels<<<BHALF / 256, 256>>>(lab, (float*)d_out);
    k_norm<<<NROWS / 8, 256>>>(zi, zj);
    k_sim<<<NCTA, 512, SMEM_BYTES>>>();
    k_final<<<NROWS / 1024, 1024>>>((float*)d_out);
}